// round 3
// baseline (speedup 1.0000x reference)
#include <cuda_runtime.h>
#include <cuda_bf16.h>
#include <cub/cub.cuh>
#include <cstdint>

// Problem: B=64 samples, each N=512*512=262144 predictions.
// Reference: per-sample, shuffle pred with jax.random.permutation(key_b) (2 rounds
// of stable sort by threefry random uint32), then rank-based AUC vs fixed labels.
//
// Strategy:
//  S0: concatenated radix sort of (sample<<32 | sortable(pred)) to get ranks
//      (tie-averaged), scattered back to original order.
//  S1, S2: two stable radix sorts by (sample<<32 | threefry_bits) carrying the
//      float rank as value == exact reproduction of jax's two sort_key_val rounds.
//  Reduce: sum over positions with t=1 of rank (2*rank is an exact small int ->
//      u64 atomics, deterministic). AUC per sample in double, mean -> d_out.

#define NSAMP 64
#define NPER  262144      // 2^18
#define HPER  131072      // 2^17
#define NTOT  (NSAMP * NPER)   // 16,777,216

__device__ uint64_t g_keysA[NTOT];
__device__ uint64_t g_keysB[NTOT];
__device__ uint32_t g_valsA[NTOT];
__device__ uint32_t g_valsB[NTOT];
__device__ float    g_rank[NTOT];
__device__ uint2    g_sub[2][NSAMP];
__device__ unsigned long long g_sum2[NSAMP];
__device__ unsigned int       g_npos[NSAMP];
__device__ __align__(256) unsigned char g_temp[440ull * 1024 * 1024];

// ---------------- threefry2x32 (exact JAX semantics) ----------------
__device__ __forceinline__ uint32_t rotl32(uint32_t v, int d) {
    return (v << d) | (v >> (32 - d));
}

__device__ __forceinline__ uint2 threefry2x32(uint32_t k0, uint32_t k1,
                                              uint32_t x0, uint32_t x1) {
    uint32_t ks0 = k0, ks1 = k1, ks2 = k0 ^ k1 ^ 0x1BD11BDAu;
    x0 += ks0; x1 += ks1;
#define TF_RND(r) { x0 += x1; x1 = rotl32(x1, r); x1 ^= x0; }
    TF_RND(13) TF_RND(15) TF_RND(26) TF_RND(6)
    x0 += ks1; x1 += ks2 + 1u;
    TF_RND(17) TF_RND(29) TF_RND(16) TF_RND(24)
    x0 += ks2; x1 += ks0 + 2u;
    TF_RND(13) TF_RND(15) TF_RND(26) TF_RND(6)
    x0 += ks0; x1 += ks1 + 3u;
    TF_RND(17) TF_RND(29) TF_RND(16) TF_RND(24)
    x0 += ks1; x1 += ks2 + 4u;
    TF_RND(13) TF_RND(15) TF_RND(26) TF_RND(6)
    x0 += ks2; x1 += ks0 + 5u;
#undef TF_RND
    return make_uint2(x0, x1);
}

// Per-sample subkeys for the two shuffle rounds.
// root = key(42) = (0, 42); sample_keys = split(root, 64);
// per sample: key,sub1 = split(key_b); _,sub2 = split(key).
__global__ void compute_subkeys_kernel() {
    int b = threadIdx.x;
    if (b >= NSAMP) return;
    const uint32_t r0 = 0u, r1 = 42u;
    // split(root, 64): counts iota(128); x0=[0..63], x1=[64..127];
    // out = [y0_0..y0_63, y1_0..y1_63]; key_b = (out[2b], out[2b+1])
    uint2 kb;
    if (b < 32) {
        kb.x = threefry2x32(r0, r1, 2 * b,     64 + 2 * b).x;
        kb.y = threefry2x32(r0, r1, 2 * b + 1, 65 + 2 * b).x;
    } else {
        kb.x = threefry2x32(r0, r1, 2 * b - 64, 2 * b).y;
        kb.y = threefry2x32(r0, r1, 2 * b - 63, 2 * b + 1).y;
    }
    // split(key, 2): counts [0,1,2,3]; lane0 = tf(k,0,2), lane1 = tf(k,1,3);
    // out = [c0,c1,d0,d1]; new_key=(c0,c1), subkey=(d0,d1)
    uint2 t0 = threefry2x32(kb.x, kb.y, 0u, 2u);
    uint2 t1 = threefry2x32(kb.x, kb.y, 1u, 3u);
    uint2 newk = make_uint2(t0.x, t1.x);
    g_sub[0][b] = make_uint2(t0.y, t1.y);
    uint2 s0 = threefry2x32(newk.x, newk.y, 0u, 2u);
    uint2 s1 = threefry2x32(newk.x, newk.y, 1u, 3u);
    g_sub[1][b] = make_uint2(s0.y, s1.y);
}

__global__ void zero_accum_kernel() {
    int b = threadIdx.x;
    if (b < NSAMP) { g_sum2[b] = 0ull; g_npos[b] = 0u; }
}

__device__ __forceinline__ uint32_t f2sortable(float f) {
    uint32_t u = __float_as_uint(f);
    return (u & 0x80000000u) ? ~u : (u | 0x80000000u);
}

// Build keys/vals for the value sort (S0).
__global__ void build_sort0_kernel(const float* __restrict__ pred) {
    int g = blockIdx.x * blockDim.x + threadIdx.x;
    if (g >= NTOT) return;
    int b = g >> 18;
    int i = g & (NPER - 1);
    g_keysA[g] = ((uint64_t)b << 32) | (uint64_t)f2sortable(pred[g]);
    g_valsA[g] = (uint32_t)i;
}

// After S0 (sorted keys in g_keysB, vals in g_valsB): compute tie-averaged
// rank of each value, scatter to original position. Keys embed the sample id,
// so equal keys are always within one segment.
__global__ void ranks_scatter_kernel() {
    int g = blockIdx.x * blockDim.x + threadIdx.x;
    if (g >= NTOT) return;
    uint64_t k = g_keysB[g];
    int a = g, e = g;
    while (a > 0        && g_keysB[a - 1] == k) a--;
    while (e < NTOT - 1 && g_keysB[e + 1] == k) e++;
    int b = g >> 18;
    int base = b << 18;
    // 0-based run [a-base, e-base] -> 1-based avg rank
    float rank = 0.5f * (float)((a - base) + (e - base) + 2);
    g_rank[base + (int)g_valsB[g]] = rank;
}

// Build shuffle-round keys: bits = threefry(sub, i, H+i) gives positions i and i+H.
__global__ void build_shuffle_keys_kernel(int round) {
    int tid = blockIdx.x * blockDim.x + threadIdx.x;
    if (tid >= NSAMP * HPER) return;
    int b = tid >> 17;
    int i = tid & (HPER - 1);
    uint2 s = g_sub[round][b];
    uint2 y = threefry2x32(s.x, s.y, (uint32_t)i, (uint32_t)(HPER + i));
    uint64_t hi = (uint64_t)b << 32;
    int g0 = (b << 18) + i;
    g_keysA[g0]        = hi | (uint64_t)y.x;
    g_keysA[g0 + HPER] = hi | (uint64_t)y.y;
}

// Final shuffled ranks live in g_valsA (as float bits). Accumulate per sample.
__global__ void reduce_kernel(const int* __restrict__ truem) {
    int g = blockIdx.x * blockDim.x + threadIdx.x;
    int b = g >> 18;
    float r = __uint_as_float(g_valsA[g]);
    int t = (truem[g] > 0) ? 1 : 0;
    // 2*rank is an exact integer <= 524289 -> exact u64 accumulation
    unsigned long long s = t ? (unsigned long long)__float2ull_rn(2.0f * r) : 0ull;
    for (int o = 16; o > 0; o >>= 1) {
        s += __shfl_down_sync(0xFFFFFFFFu, s, o);
        t += __shfl_down_sync(0xFFFFFFFFu, t, o);
    }
    __shared__ unsigned long long ss[8];
    __shared__ int st[8];
    int lane = threadIdx.x & 31, w = threadIdx.x >> 5;
    if (lane == 0) { ss[w] = s; st[w] = t; }
    __syncthreads();
    if (threadIdx.x == 0) {
        unsigned long long bs = 0ull; int bt = 0;
        #pragma unroll
        for (int k = 0; k < 8; k++) { bs += ss[k]; bt += st[k]; }
        atomicAdd(&g_sum2[b], bs);
        atomicAdd(&g_npos[b], (unsigned int)bt);
    }
}

__global__ void finalize_kernel(float* __restrict__ out) {
    __shared__ double aucs[NSAMP];
    int b = threadIdx.x;
    if (b < NSAMP) {
        double np = (double)g_npos[b];
        double nn = (double)NPER - np;
        double spr = 0.5 * (double)g_sum2[b];
        aucs[b] = (spr - np * (np + 1.0) * 0.5) / (np * nn);
    }
    __syncthreads();
    if (b == 0) {
        double tot = 0.0;
        for (int k = 0; k < NSAMP; k++) tot += aucs[k];
        out[0] = (float)(tot / (double)NSAMP);
    }
}

extern "C" void kernel_launch(void* const* d_in, const int* in_sizes, int n_in,
                              void* d_out, int out_size) {
    const float* pred  = (const float*)d_in[0];
    const int*   truem = (const int*)d_in[1];
    float*       out   = (float*)d_out;
    cudaStream_t st = 0;

    uint64_t *kA, *kB;
    uint32_t *vA, *vB;
    float* rk;
    void* tmp;
    cudaGetSymbolAddress((void**)&kA, g_keysA);
    cudaGetSymbolAddress((void**)&kB, g_keysB);
    cudaGetSymbolAddress((void**)&vA, g_valsA);
    cudaGetSymbolAddress((void**)&vB, g_valsB);
    cudaGetSymbolAddress((void**)&rk, g_rank);
    cudaGetSymbolAddress(&tmp, g_temp);
    size_t cap = sizeof(g_temp);

    const int TPB = 256;
    const int GRID_ALL  = NTOT / TPB;          // 65536
    const int GRID_HALF = (NSAMP * HPER) / TPB; // 32768

    zero_accum_kernel<<<1, 64, 0, st>>>();
    compute_subkeys_kernel<<<1, 64, 0, st>>>();

    // ---- S0: sort by pred value (per segment) for ranks ----
    build_sort0_kernel<<<GRID_ALL, TPB, 0, st>>>(pred);
    {
        size_t need = 0;
        cub::DeviceRadixSort::SortPairs(nullptr, need, kA, kB, vA, vB,
                                        NTOT, 0, 38, st);
        if (need > cap) return;  // would fail loudly in bench
        cub::DeviceRadixSort::SortPairs(tmp, cap, kA, kB, vA, vB,
                                        NTOT, 0, 38, st);
    }
    ranks_scatter_kernel<<<GRID_ALL, TPB, 0, st>>>();

    // ---- S1: shuffle round 1 (vals = ranks in original order) ----
    build_shuffle_keys_kernel<<<GRID_HALF, TPB, 0, st>>>(0);
    {
        size_t need = 0;
        cub::DeviceRadixSort::SortPairs(nullptr, need, kA, kB,
                                        (const uint32_t*)rk, vB, NTOT, 0, 38, st);
        if (need > cap) return;
        cub::DeviceRadixSort::SortPairs(tmp, cap, kA, kB,
                                        (const uint32_t*)rk, vB, NTOT, 0, 38, st);
    }

    // ---- S2: shuffle round 2 (vals = round-1 output in g_valsB) ----
    build_shuffle_keys_kernel<<<GRID_HALF, TPB, 0, st>>>(1);
    {
        size_t need = 0;
        cub::DeviceRadixSort::SortPairs(nullptr, need, kA, kB, vB, vA,
                                        NTOT, 0, 38, st);
        if (need > cap) return;
        cub::DeviceRadixSort::SortPairs(tmp, cap, kA, kB, vB, vA,
                                        NTOT, 0, 38, st);
    }

    // ---- reduce + finalize ----
    reduce_kernel<<<GRID_ALL, TPB, 0, st>>>(truem);
    finalize_kernel<<<1, 64, 0, st>>>(out);
}

// round 5
// speedup vs baseline: 1.6446x; 1.6446x over previous
#include <cuda_runtime.h>
#include <cuda_bf16.h>
#include <cub/cub.cuh>
#include <cstdint>

// AUCShuffled: B=64 samples x N=2^18 preds.
// answer_b = sum_k rank0[k] * t[r2[r1[k]]]  (r1,r2 = stable ranks of threefry keys)
//  - r1,r2 via bucket-counting rank (keys uniform u32) -> no comparison sort
//  - rank0 via ONE CUB 32-bit keys-only sort with the label bit packed in the key

#define NSAMP 64
#define NPER  262144            // 2^18
#define HPER  131072            // 2^17
#define NTOT  (NSAMP * NPER)    // 16,777,216
#define NBUCK 65536             // 2^16 buckets per sample (top 16 key bits)
#define NHIST (NSAMP * NBUCK)   // 4,194,304
#define CHUNK 4096
#define NCHUNK (NHIST / CHUNK)  // 1024

__device__ uint64_t g_rec[NTOT];        // (key<<18)|local_idx, bucket-grouped
__device__ uint32_t g_skA[NTOT];        // S0 keys in
__device__ uint32_t g_skB[NTOT];        // rank2 storage, then S0 keys out
__device__ uint32_t g_hist[NHIST];      // bucket counts -> chunk-local exclusive prefix
__device__ uint32_t g_c2[NHIST];        // scatter offsets / final counts
__device__ uint32_t g_chunkSum[NCHUNK];
__device__ uint32_t g_chunkBase[NCHUNK];
__device__ uint8_t  g_t8[NTOT];
__device__ uint8_t  g_lam[NTOT];        // lambda[i] = t[r2[i]]
__device__ uint8_t  g_m[NTOT];          // m[k] = lam[r1[k]]
__device__ uint2    g_sub[2][NSAMP];
__device__ unsigned long long g_sum[NSAMP];
__device__ unsigned int       g_npos[NSAMP];
// CUB SortKeys with separate in/out pointers allocates an internal alternate
// keys buffer in temp storage: need ~= NTOT*4B + overhead ~= 68MB. 160MB cap.
__device__ __align__(256) unsigned char g_temp[160ull * 1024 * 1024];

// ---------------- threefry2x32 (exact JAX semantics) ----------------
__device__ __forceinline__ uint32_t rotl32(uint32_t v, int d) {
    return (v << d) | (v >> (32 - d));
}
__device__ __forceinline__ uint2 threefry2x32(uint32_t k0, uint32_t k1,
                                              uint32_t x0, uint32_t x1) {
    uint32_t ks0 = k0, ks1 = k1, ks2 = k0 ^ k1 ^ 0x1BD11BDAu;
    x0 += ks0; x1 += ks1;
#define TF_RND(r) { x0 += x1; x1 = rotl32(x1, r); x1 ^= x0; }
    TF_RND(13) TF_RND(15) TF_RND(26) TF_RND(6)
    x0 += ks1; x1 += ks2 + 1u;
    TF_RND(17) TF_RND(29) TF_RND(16) TF_RND(24)
    x0 += ks2; x1 += ks0 + 2u;
    TF_RND(13) TF_RND(15) TF_RND(26) TF_RND(6)
    x0 += ks0; x1 += ks1 + 3u;
    TF_RND(17) TF_RND(29) TF_RND(16) TF_RND(24)
    x0 += ks1; x1 += ks2 + 4u;
    TF_RND(13) TF_RND(15) TF_RND(26) TF_RND(6)
    x0 += ks2; x1 += ks0 + 5u;
#undef TF_RND
    return make_uint2(x0, x1);
}

// init: zero accumulators + compute per-sample subkeys (validated in R0-R3 kernel)
__global__ void init_kernel() {
    int b = threadIdx.x;
    if (b >= NSAMP) return;
    g_sum[b]  = 0ull;
    g_npos[b] = 0u;
    const uint32_t r0 = 0u, r1 = 42u;
    uint2 kb;
    if (b < 32) {
        kb.x = threefry2x32(r0, r1, 2 * b,     64 + 2 * b).x;
        kb.y = threefry2x32(r0, r1, 2 * b + 1, 65 + 2 * b).x;
    } else {
        kb.x = threefry2x32(r0, r1, 2 * b - 64, 2 * b).y;
        kb.y = threefry2x32(r0, r1, 2 * b - 63, 2 * b + 1).y;
    }
    uint2 t0 = threefry2x32(kb.x, kb.y, 0u, 2u);
    uint2 t1 = threefry2x32(kb.x, kb.y, 1u, 3u);
    uint2 newk = make_uint2(t0.x, t1.x);
    g_sub[0][b] = make_uint2(t0.y, t1.y);          // round-1 subkey
    uint2 s0 = threefry2x32(newk.x, newk.y, 0u, 2u);
    uint2 s1 = threefry2x32(newk.x, newk.y, 1u, 3u);
    g_sub[1][b] = make_uint2(s0.y, s1.y);          // round-2 subkey
}

// labels -> bytes + per-sample positive count. ITEMS=8 per thread.
__global__ void t8_kernel(const int* __restrict__ truem) {
    int base = (blockIdx.x * blockDim.x + threadIdx.x) * 8;
    int b = base >> 18;              // block covers 2048 consecutive: single sample
    unsigned cnt = 0;
    #pragma unroll
    for (int k = 0; k < 8; k++) {
        int v = (truem[base + k] > 0) ? 1 : 0;
        g_t8[base + k] = (uint8_t)v;
        cnt += v;
    }
    for (int o = 16; o > 0; o >>= 1) cnt += __shfl_down_sync(0xFFFFFFFFu, cnt, o);
    __shared__ unsigned sc[8];
    int lane = threadIdx.x & 31, w = threadIdx.x >> 5;
    if (lane == 0) sc[w] = cnt;
    __syncthreads();
    if (threadIdx.x == 0) {
        unsigned s = 0;
        #pragma unroll
        for (int k = 0; k < 8; k++) s += sc[k];
        atomicAdd(&g_npos[b], s);
    }
}

// histogram of top-16 key bits (keys generated on the fly)
__global__ void hist_kernel(int round) {
    int i = blockIdx.x * blockDim.x + threadIdx.x;  // [0, NSAMP*HPER)
    int b = i >> 17, loc = i & (HPER - 1);
    uint2 s = g_sub[round][b];
    uint2 y = threefry2x32(s.x, s.y, (uint32_t)loc, (uint32_t)(HPER + loc));
    atomicAdd(&g_hist[(b << 16) + (y.x >> 16)], 1u);
    atomicAdd(&g_hist[(b << 16) + (y.y >> 16)], 1u);
}

// chunk-local exclusive scan of g_hist (in place), chunk totals out
__global__ void scanA_kernel() {
    typedef cub::BlockScan<uint32_t, 256> BS;
    __shared__ typename BS::TempStorage ts;
    int base = blockIdx.x * CHUNK + threadIdx.x * 16;
    uint32_t v[16]; uint32_t s = 0;
    #pragma unroll
    for (int k = 0; k < 16; k++) { v[k] = g_hist[base + k]; s += v[k]; }
    uint32_t ex, tot;
    BS(ts).ExclusiveSum(s, ex, tot);
    uint32_t run = ex;
    #pragma unroll
    for (int k = 0; k < 16; k++) { uint32_t t = v[k]; g_hist[base + k] = run; run += t; }
    if (threadIdx.x == 0) g_chunkSum[blockIdx.x] = tot;
}

// per-sample exclusive scan over each sample's 16 chunk sums
__global__ void scanB_kernel() {
    int t = threadIdx.x;               // 0..1023
    int smp = t >> 4, pos = t & 15;
    uint32_t acc = 0;
    for (int j = 0; j < pos; j++) acc += g_chunkSum[(smp << 4) + j];
    g_chunkBase[t] = acc;
}

__device__ __forceinline__ uint32_t bucket_base(int b, uint32_t bucket) {
    return g_hist[(b << 16) + bucket] + g_chunkBase[(b << 4) | (bucket >> 12)];
}

// scatter (key<<18|idx) records into bucket-grouped slots
__global__ void scatter_kernel(int round) {
    int i = blockIdx.x * blockDim.x + threadIdx.x;
    int b = i >> 17, loc = i & (HPER - 1);
    uint2 s = g_sub[round][b];
    uint2 y = threefry2x32(s.x, s.y, (uint32_t)loc, (uint32_t)(HPER + loc));
    {
        uint32_t key = y.x, bucket = key >> 16;
        uint32_t p = bucket_base(b, bucket);
        uint32_t off = atomicAdd(&g_c2[(b << 16) + bucket], 1u);
        g_rec[(b << 18) + p + off] = ((uint64_t)key << 18) | (uint32_t)loc;
    }
    {
        uint32_t key = y.y, bucket = key >> 16;
        uint32_t p = bucket_base(b, bucket);
        uint32_t off = atomicAdd(&g_c2[(b << 16) + bucket], 1u);
        g_rec[(b << 18) + p + off] = ((uint64_t)key << 18) | (uint32_t)(HPER + loc);
    }
}

// within-bucket stable rank by direct u64 comparison (atomics-order independent).
// phase==2: write rank2 into g_skB.  phase==1: write m = lam[rank].
__global__ void rank_kernel(int phase) {
    int g = blockIdx.x * blockDim.x + threadIdx.x;
    uint64_t me = g_rec[g];
    int b = g >> 18;
    uint32_t key = (uint32_t)(me >> 18);
    uint32_t bucket = key >> 16;
    uint32_t p = bucket_base(b, bucket);
    uint32_t cnt = g_c2[(b << 16) + bucket];
    int base = (b << 18) + (int)p;
    uint32_t r = 0;
    for (uint32_t j = 0; j < cnt; j++) r += (g_rec[base + j] < me) ? 1u : 0u;
    uint32_t il = (uint32_t)(me & 0x3FFFFu);
    uint32_t rank = p + r;                 // 0-based stable rank within sample
    if (phase == 2) g_skB[(b << 18) + il] = rank;
    else            g_m[(b << 18) + il]   = g_lam[(b << 18) + rank];
}

// lam[i] = t8[r2[i]]
__global__ void lambda_kernel() {
    int g = blockIdx.x * blockDim.x + threadIdx.x;
    int b = g >> 18;
    g_lam[g] = g_t8[(b << 18) + g_skB[g]];
}

__device__ __forceinline__ uint32_t f2sortable(float f) {
    uint32_t u = __float_as_uint(f);
    return (u & 0x80000000u) ? ~u : (u | 0x80000000u);
}

// S0 key: (sample:6 | pred>>7 :25 | m:1)
__global__ void build_s0_kernel(const float* __restrict__ pred) {
    int g = blockIdx.x * blockDim.x + threadIdx.x;
    uint32_t b = (uint32_t)(g >> 18);
    uint32_t k25 = f2sortable(pred[g]) >> 7;
    g_skA[g] = (b << 26) | (k25 << 1) | (uint32_t)g_m[g];
}

// sorted keys: segment b = [b<<18,(b+1)<<18); rank = (g&0x3FFFF)+1; label = key&1
__global__ void reduce_kernel() {
    int base = (blockIdx.x * blockDim.x + threadIdx.x) * 8;
    int b = base >> 18;   // 2048-aligned blocks: single sample
    unsigned long long s = 0ull;
    #pragma unroll
    for (int k = 0; k < 8; k++) {
        uint32_t key = g_skB[base + k];
        s += (key & 1u) ? (unsigned long long)(((base + k) & 0x3FFFF) + 1) : 0ull;
    }
    for (int o = 16; o > 0; o >>= 1) s += __shfl_down_sync(0xFFFFFFFFu, s, o);
    __shared__ unsigned long long sc[8];
    int lane = threadIdx.x & 31, w = threadIdx.x >> 5;
    if (lane == 0) sc[w] = s;
    __syncthreads();
    if (threadIdx.x == 0) {
        unsigned long long t = 0ull;
        #pragma unroll
        for (int k = 0; k < 8; k++) t += sc[k];
        atomicAdd(&g_sum[b], t);
    }
}

__global__ void finalize_kernel(float* __restrict__ out) {
    __shared__ double aucs[NSAMP];
    int b = threadIdx.x;
    if (b < NSAMP) {
        double np = (double)g_npos[b];
        double nn = (double)NPER - np;
        double spr = (double)g_sum[b];
        aucs[b] = (spr - np * (np + 1.0) * 0.5) / (np * nn);
    }
    __syncthreads();
    if (b == 0) {
        double tot = 0.0;
        for (int k = 0; k < NSAMP; k++) tot += aucs[k];
        out[0] = (float)(tot / (double)NSAMP);
    }
}

extern "C" void kernel_launch(void* const* d_in, const int* in_sizes, int n_in,
                              void* d_out, int out_size) {
    const float* pred  = (const float*)d_in[0];
    const int*   truem = (const int*)d_in[1];
    float*       out   = (float*)d_out;
    cudaStream_t st = 0;

    uint32_t *skA, *skB, *hist, *c2;
    void* tmp;
    cudaGetSymbolAddress((void**)&skA, g_skA);
    cudaGetSymbolAddress((void**)&skB, g_skB);
    cudaGetSymbolAddress((void**)&hist, g_hist);
    cudaGetSymbolAddress((void**)&c2, g_c2);
    cudaGetSymbolAddress(&tmp, g_temp);
    size_t cap = sizeof(g_temp);

    const int TPB = 256;
    const int GRID_ALL  = NTOT / TPB;                 // 65536
    const int GRID_HALF = (NSAMP * HPER) / TPB;       // 32768
    const int GRID_8    = NTOT / (TPB * 8);           // 8192

    init_kernel<<<1, 64, 0, st>>>();
    t8_kernel<<<GRID_8, TPB, 0, st>>>(truem);

    // ---- round 2 ranks (sub[1]) ----
    cudaMemsetAsync(hist, 0, NHIST * 4, st);
    cudaMemsetAsync(c2,   0, NHIST * 4, st);
    hist_kernel<<<GRID_HALF, TPB, 0, st>>>(1);
    scanA_kernel<<<NCHUNK, 256, 0, st>>>();
    scanB_kernel<<<1, NCHUNK, 0, st>>>();
    scatter_kernel<<<GRID_HALF, TPB, 0, st>>>(1);
    rank_kernel<<<GRID_ALL, TPB, 0, st>>>(2);
    lambda_kernel<<<GRID_ALL, TPB, 0, st>>>();

    // ---- round 1 ranks (sub[0]) -> m ----
    cudaMemsetAsync(hist, 0, NHIST * 4, st);
    cudaMemsetAsync(c2,   0, NHIST * 4, st);
    hist_kernel<<<GRID_HALF, TPB, 0, st>>>(0);
    scanA_kernel<<<NCHUNK, 256, 0, st>>>();
    scanB_kernel<<<1, NCHUNK, 0, st>>>();
    scatter_kernel<<<GRID_HALF, TPB, 0, st>>>(0);
    rank_kernel<<<GRID_ALL, TPB, 0, st>>>(1);

    // ---- S0: one 32-bit keys-only sort + reduce ----
    build_s0_kernel<<<GRID_ALL, TPB, 0, st>>>(pred);
    {
        size_t need = 0;
        cub::DeviceRadixSort::SortKeys(nullptr, need, skA, skB, NTOT, 0, 32, st);
        if (need > cap) return;  // fails loudly in bench (out stays poisoned)
        cub::DeviceRadixSort::SortKeys(tmp, cap, skA, skB, NTOT, 0, 32, st);
    }
    reduce_kernel<<<GRID_8, TPB, 0, st>>>();
    finalize_kernel<<<1, 64, 0, st>>>(out);
}

// round 6
// speedup vs baseline: 1.7578x; 1.0689x over previous
#include <cuda_runtime.h>
#include <cuda_bf16.h>
#include <cub/cub.cuh>
#include <cstdint>

// AUCShuffled: B=64 samples x N=2^18 preds.
// answer_b = sum_k rank0[k] * t[r2[r1[k]]]  (r1,r2 = stable ranks of threefry keys)
//  - r1,r2 via bucket-counting rank (keys uniform u32) -> no comparison sort
//  - rank0 via ONE CUB 32-bit keys-only sort with the label bit packed in the key
// R6: fused lambda into rank, cached threefry keys, vectorized scan/t8/reduce,
//     merged both shuffle rounds into combined hist/scan/scatter kernels.

#define NSAMP 64
#define NPER  262144            // 2^18
#define HPER  131072            // 2^17
#define NTOT  (NSAMP * NPER)    // 16,777,216
#define NBUCK 65536             // 2^16 buckets per sample (top 16 key bits)
#define NHIST (NSAMP * NBUCK)   // 4,194,304 per round
#define CHUNK 4096
#define NCHUNK2 ((2 * NHIST) / CHUNK)  // 2048 chunks over both rounds

// counters: [hist round0 | hist round1 | c2 round0 | c2 round1]
__device__ uint32_t g_cnt[4 * NHIST];          // 64MB, one memset
__device__ uint64_t g_recA[NTOT];              // round-0 records (key<<18)|idx
__device__ uint64_t g_recB[NTOT];              // round-1 records
__device__ uint32_t g_skA[NTOT];               // round-0 keys, later S0 keys in
__device__ uint32_t g_skB[NTOT];               // round-1 keys, later S0 keys out
__device__ uint32_t g_chunkSum[NCHUNK2];
__device__ uint32_t g_chunkBase[NCHUNK2];
__device__ uint8_t  g_t8[NTOT];
__device__ uint8_t  g_lam[NTOT];               // lam[i] = t[r2[i]]
__device__ uint8_t  g_m[NTOT];                 // m[k] = lam[r1[k]]
__device__ uint2    g_sub[2][NSAMP];
__device__ unsigned long long g_sum[NSAMP];
__device__ unsigned int       g_npos[NSAMP];
// CUB SortKeys (separate in/out) allocates an alternate keys buffer in temp:
// need ~= NTOT*4B + overhead ~= 68MB.
__device__ __align__(256) unsigned char g_temp[160ull * 1024 * 1024];

// ---------------- threefry2x32 (exact JAX semantics) ----------------
__device__ __forceinline__ uint32_t rotl32(uint32_t v, int d) {
    return (v << d) | (v >> (32 - d));
}
__device__ __forceinline__ uint2 threefry2x32(uint32_t k0, uint32_t k1,
                                              uint32_t x0, uint32_t x1) {
    uint32_t ks0 = k0, ks1 = k1, ks2 = k0 ^ k1 ^ 0x1BD11BDAu;
    x0 += ks0; x1 += ks1;
#define TF_RND(r) { x0 += x1; x1 = rotl32(x1, r); x1 ^= x0; }
    TF_RND(13) TF_RND(15) TF_RND(26) TF_RND(6)
    x0 += ks1; x1 += ks2 + 1u;
    TF_RND(17) TF_RND(29) TF_RND(16) TF_RND(24)
    x0 += ks2; x1 += ks0 + 2u;
    TF_RND(13) TF_RND(15) TF_RND(26) TF_RND(6)
    x0 += ks0; x1 += ks1 + 3u;
    TF_RND(17) TF_RND(29) TF_RND(16) TF_RND(24)
    x0 += ks1; x1 += ks2 + 4u;
    TF_RND(13) TF_RND(15) TF_RND(26) TF_RND(6)
    x0 += ks2; x1 += ks0 + 5u;
#undef TF_RND
    return make_uint2(x0, x1);
}

// init: zero accumulators + per-sample subkeys (validated in earlier rounds)
__global__ void init_kernel() {
    int b = threadIdx.x;
    if (b >= NSAMP) return;
    g_sum[b]  = 0ull;
    g_npos[b] = 0u;
    const uint32_t r0 = 0u, r1 = 42u;
    uint2 kb;
    if (b < 32) {
        kb.x = threefry2x32(r0, r1, 2 * b,     64 + 2 * b).x;
        kb.y = threefry2x32(r0, r1, 2 * b + 1, 65 + 2 * b).x;
    } else {
        kb.x = threefry2x32(r0, r1, 2 * b - 64, 2 * b).y;
        kb.y = threefry2x32(r0, r1, 2 * b - 63, 2 * b + 1).y;
    }
    uint2 t0 = threefry2x32(kb.x, kb.y, 0u, 2u);
    uint2 t1 = threefry2x32(kb.x, kb.y, 1u, 3u);
    uint2 newk = make_uint2(t0.x, t1.x);
    g_sub[0][b] = make_uint2(t0.y, t1.y);          // round-1 (first shuffle sort)
    uint2 s0 = threefry2x32(newk.x, newk.y, 0u, 2u);
    uint2 s1 = threefry2x32(newk.x, newk.y, 1u, 3u);
    g_sub[1][b] = make_uint2(s0.y, s1.y);          // round-2 (second shuffle sort)
}

// labels -> bytes + per-sample positive count. int4-vectorized, 8/thread.
__global__ void t8_kernel(const int* __restrict__ truem) {
    int base = (blockIdx.x * blockDim.x + threadIdx.x) * 8;
    int b = base >> 18;
    int4 v0 = *reinterpret_cast<const int4*>(truem + base);
    int4 v1 = *reinterpret_cast<const int4*>(truem + base + 4);
    uchar4 c0, c1;
    c0.x = v0.x > 0; c0.y = v0.y > 0; c0.z = v0.z > 0; c0.w = v0.w > 0;
    c1.x = v1.x > 0; c1.y = v1.y > 0; c1.z = v1.z > 0; c1.w = v1.w > 0;
    *reinterpret_cast<uchar4*>(g_t8 + base)     = c0;
    *reinterpret_cast<uchar4*>(g_t8 + base + 4) = c1;
    unsigned cnt = (unsigned)(c0.x + c0.y + c0.z + c0.w + c1.x + c1.y + c1.z + c1.w);
    for (int o = 16; o > 0; o >>= 1) cnt += __shfl_down_sync(0xFFFFFFFFu, cnt, o);
    __shared__ unsigned sc[8];
    int lane = threadIdx.x & 31, w = threadIdx.x >> 5;
    if (lane == 0) sc[w] = cnt;
    __syncthreads();
    if (threadIdx.x == 0) {
        unsigned s = 0;
        #pragma unroll
        for (int k = 0; k < 8; k++) s += sc[k];
        atomicAdd(&g_npos[b], s);
    }
}

// Compute threefry keys for BOTH rounds, cache them, and histogram top-16 bits.
__global__ void keys_hist_kernel() {
    int i = blockIdx.x * blockDim.x + threadIdx.x;  // [0, NSAMP*HPER)
    int b = i >> 17, loc = i & (HPER - 1);
    int g0 = (b << 18) + loc;
    #pragma unroll
    for (int r = 0; r < 2; r++) {
        uint2 s = g_sub[r][b];
        uint2 y = threefry2x32(s.x, s.y, (uint32_t)loc, (uint32_t)(HPER + loc));
        uint32_t* keys = r ? g_skB : g_skA;
        keys[g0]        = y.x;
        keys[g0 + HPER] = y.y;
        uint32_t* h = g_cnt + r * NHIST + (b << 16);
        atomicAdd(&h[y.x >> 16], 1u);
        atomicAdd(&h[y.y >> 16], 1u);
    }
}

// chunk-local exclusive scan of g_cnt[0 .. 2*NHIST) in place; chunk totals out.
__global__ void scanA_kernel() {
    typedef cub::BlockScan<uint32_t, 256> BS;
    __shared__ typename BS::TempStorage ts;
    int base = blockIdx.x * CHUNK + threadIdx.x * 16;
    uint4 v[4];
    #pragma unroll
    for (int q = 0; q < 4; q++)
        v[q] = *reinterpret_cast<const uint4*>(g_cnt + base + q * 4);
    uint32_t s = 0;
    #pragma unroll
    for (int q = 0; q < 4; q++) s += v[q].x + v[q].y + v[q].z + v[q].w;
    uint32_t ex, tot;
    BS(ts).ExclusiveSum(s, ex, tot);
    uint32_t run = ex;
    #pragma unroll
    for (int q = 0; q < 4; q++) {
        uint4 o;
        o.x = run; run += v[q].x;
        o.y = run; run += v[q].y;
        o.z = run; run += v[q].z;
        o.w = run; run += v[q].w;
        *reinterpret_cast<uint4*>(g_cnt + base + q * 4) = o;
    }
    if (threadIdx.x == 0) g_chunkSum[blockIdx.x] = tot;
}

// per (round,sample) exclusive scan over its 16 chunk sums
__global__ void scanB_kernel() {
    int t = threadIdx.x + blockIdx.x * blockDim.x;  // 0..2047
    if (t >= NCHUNK2) return;
    int rs = t >> 4, pos = t & 15;
    uint32_t acc = 0;
    for (int j = 0; j < pos; j++) acc += g_chunkSum[(rs << 4) + j];
    g_chunkBase[t] = acc;
}

__device__ __forceinline__ uint32_t bucket_base(int r, int b, uint32_t bucket) {
    return g_cnt[r * NHIST + (b << 16) + bucket] +
           g_chunkBase[((r * NSAMP + b) << 4) | (bucket >> 12)];
}

// scatter (key<<18|idx) records into bucket-grouped slots, both rounds
__global__ void scatter_kernel() {
    int i = blockIdx.x * blockDim.x + threadIdx.x;
    int b = i >> 17, loc = i & (HPER - 1);
    int g0 = (b << 18) + loc;
    #pragma unroll
    for (int r = 0; r < 2; r++) {
        const uint32_t* keys = r ? g_skB : g_skA;
        uint64_t* rec = r ? g_recB : g_recA;
        uint32_t* c2 = g_cnt + (2 + r) * NHIST + (b << 16);
        uint32_t k0 = keys[g0], k1 = keys[g0 + HPER];
        {
            uint32_t bucket = k0 >> 16;
            uint32_t p = bucket_base(r, b, bucket);
            uint32_t off = atomicAdd(&c2[bucket], 1u);
            rec[(b << 18) + p + off] = ((uint64_t)k0 << 18) | (uint32_t)loc;
        }
        {
            uint32_t bucket = k1 >> 16;
            uint32_t p = bucket_base(r, b, bucket);
            uint32_t off = atomicAdd(&c2[bucket], 1u);
            rec[(b << 18) + p + off] = ((uint64_t)k1 << 18) | (uint32_t)(HPER + loc);
        }
    }
}

// within-bucket stable rank by direct u64 comparison (atomics-order independent).
// R==1 (round 2): lam[il] = t8[rank].   R==0 (round 1): m[il] = lam[rank].
template <int R>
__global__ void rank_kernel() {
    int g = blockIdx.x * blockDim.x + threadIdx.x;
    const uint64_t* rec = R ? g_recB : g_recA;
    uint64_t me = rec[g];
    int b = g >> 18;
    uint32_t key = (uint32_t)(me >> 18);
    uint32_t bucket = key >> 16;
    uint32_t p = bucket_base(R, b, bucket);
    uint32_t cnt = g_cnt[(2 + R) * NHIST + (b << 16) + bucket];
    int base = (b << 18) + (int)p;
    uint32_t r = 0;
    for (uint32_t j = 0; j < cnt; j++) r += (rec[base + j] < me) ? 1u : 0u;
    uint32_t il = (uint32_t)(me & 0x3FFFFu);
    uint32_t rank = p + r;                 // 0-based stable rank within sample
    if (R == 1) g_lam[(b << 18) + il] = g_t8[(b << 18) + rank];   // near-coalesced gather
    else        g_m[(b << 18) + il]   = g_lam[(b << 18) + rank];
}

__device__ __forceinline__ uint32_t f2sortable(float f) {
    uint32_t u = __float_as_uint(f);
    return (u & 0x80000000u) ? ~u : (u | 0x80000000u);
}

// S0 key: (sample:6 | pred>>7 :25 | m:1), 4 elements per thread
__global__ void build_s0_kernel(const float* __restrict__ pred) {
    int base = (blockIdx.x * blockDim.x + threadIdx.x) * 4;
    uint32_t b = (uint32_t)(base >> 18);
    float4 p = *reinterpret_cast<const float4*>(pred + base);
    uchar4 m = *reinterpret_cast<const uchar4*>(g_m + base);
    uint4 o;
    o.x = (b << 26) | ((f2sortable(p.x) >> 7) << 1) | (uint32_t)m.x;
    o.y = (b << 26) | ((f2sortable(p.y) >> 7) << 1) | (uint32_t)m.y;
    o.z = (b << 26) | ((f2sortable(p.z) >> 7) << 1) | (uint32_t)m.z;
    o.w = (b << 26) | ((f2sortable(p.w) >> 7) << 1) | (uint32_t)m.w;
    *reinterpret_cast<uint4*>(g_skA + base) = o;
}

// sorted keys: segment b = [b<<18,(b+1)<<18); rank = (g&0x3FFFF)+1; label = key&1
__global__ void reduce_kernel() {
    int base = (blockIdx.x * blockDim.x + threadIdx.x) * 8;
    int b = base >> 18;
    uint4 v0 = *reinterpret_cast<const uint4*>(g_skB + base);
    uint4 v1 = *reinterpret_cast<const uint4*>(g_skB + base + 4);
    unsigned long long s = 0ull;
    int loc = base & 0x3FFFF;
    s += (v0.x & 1u) ? (unsigned long long)(loc + 1) : 0ull;
    s += (v0.y & 1u) ? (unsigned long long)(loc + 2) : 0ull;
    s += (v0.z & 1u) ? (unsigned long long)(loc + 3) : 0ull;
    s += (v0.w & 1u) ? (unsigned long long)(loc + 4) : 0ull;
    s += (v1.x & 1u) ? (unsigned long long)(loc + 5) : 0ull;
    s += (v1.y & 1u) ? (unsigned long long)(loc + 6) : 0ull;
    s += (v1.z & 1u) ? (unsigned long long)(loc + 7) : 0ull;
    s += (v1.w & 1u) ? (unsigned long long)(loc + 8) : 0ull;
    for (int o = 16; o > 0; o >>= 1) s += __shfl_down_sync(0xFFFFFFFFu, s, o);
    __shared__ unsigned long long sc[8];
    int lane = threadIdx.x & 31, w = threadIdx.x >> 5;
    if (lane == 0) sc[w] = s;
    __syncthreads();
    if (threadIdx.x == 0) {
        unsigned long long t = 0ull;
        #pragma unroll
        for (int k = 0; k < 8; k++) t += sc[k];
        atomicAdd(&g_sum[b], t);
    }
}

__global__ void finalize_kernel(float* __restrict__ out) {
    __shared__ double aucs[NSAMP];
    int b = threadIdx.x;
    if (b < NSAMP) {
        double np = (double)g_npos[b];
        double nn = (double)NPER - np;
        double spr = (double)g_sum[b];
        aucs[b] = (spr - np * (np + 1.0) * 0.5) / (np * nn);
    }
    __syncthreads();
    if (b == 0) {
        double tot = 0.0;
        for (int k = 0; k < NSAMP; k++) tot += aucs[k];
        out[0] = (float)(tot / (double)NSAMP);
    }
}

extern "C" void kernel_launch(void* const* d_in, const int* in_sizes, int n_in,
                              void* d_out, int out_size) {
    const float* pred  = (const float*)d_in[0];
    const int*   truem = (const int*)d_in[1];
    float*       out   = (float*)d_out;
    cudaStream_t st = 0;

    uint32_t *skA, *skB, *cnt;
    void* tmp;
    cudaGetSymbolAddress((void**)&skA, g_skA);
    cudaGetSymbolAddress((void**)&skB, g_skB);
    cudaGetSymbolAddress((void**)&cnt, g_cnt);
    cudaGetSymbolAddress(&tmp, g_temp);
    size_t cap = sizeof(g_temp);

    const int TPB = 256;
    const int GRID_ALL  = NTOT / TPB;                 // 65536
    const int GRID_HALF = (NSAMP * HPER) / TPB;       // 32768
    const int GRID_8    = NTOT / (TPB * 8);           // 8192
    const int GRID_4    = NTOT / (TPB * 4);           // 16384

    init_kernel<<<1, 64, 0, st>>>();
    t8_kernel<<<GRID_8, TPB, 0, st>>>(truem);
    cudaMemsetAsync(cnt, 0, 4ull * NHIST * 4, st);

    // ---- both shuffle rounds: keys+hist, scan, scatter ----
    keys_hist_kernel<<<GRID_HALF, TPB, 0, st>>>();
    scanA_kernel<<<NCHUNK2, 256, 0, st>>>();
    scanB_kernel<<<NCHUNK2 / 256, 256, 0, st>>>();
    scatter_kernel<<<GRID_HALF, TPB, 0, st>>>();
    rank_kernel<1><<<GRID_ALL, TPB, 0, st>>>();   // lam[i] = t8[r2[i]]
    rank_kernel<0><<<GRID_ALL, TPB, 0, st>>>();   // m[k] = lam[r1[k]]

    // ---- S0: one 32-bit keys-only sort + reduce ----
    build_s0_kernel<<<GRID_4, TPB, 0, st>>>(pred);
    {
        size_t need = 0;
        cub::DeviceRadixSort::SortKeys(nullptr, need, skA, skB, NTOT, 0, 32, st);
        if (need > cap) return;  // fails loudly in bench (out stays poisoned)
        cub::DeviceRadixSort::SortKeys(tmp, cap, skA, skB, NTOT, 0, 32, st);
    }
    reduce_kernel<<<GRID_8, TPB, 0, st>>>();
    finalize_kernel<<<1, 64, 0, st>>>(out);
}